// round 1
// baseline (speedup 1.0000x reference)
#include <cuda_runtime.h>
#include <math.h>

#define E_ 172
#define DE_ 172
#define KNB 20
#define HH 2
#define HD_ 86
#define KVD 344           // E + DE
#define NNODES_ 100000
#define BMAX 12000
#define NT 352

// Scratch (allocation-free rule: __device__ globals)
__device__ float g_h1[BMAX * E_];      // layer-1 output h
__device__ int   g_owner[NNODES_];     // last sample index that scattered into each node (-1 = none)

struct Smem {
  float t[E_];
  float qin[E_];
  float q[E_];
  float outv[E_];
  float kv[KNB][KVD];
  float kk[KNB][E_];
  float vv[KNB][E_];
  float scores[HH][KNB];
  float attn[HH][KNB];
  const float* nbrp[KNB];
  const float* efp[KNB];
  int pad[KNB];
};

__global__ void init_owner_kernel() {
  int i = blockIdx.x * blockDim.x + threadIdx.x;
  if (i < NNODES_) g_owner[i] = -1;
}

__global__ void build_owner_kernel(const int* __restrict__ nodes, int B) {
  int i = blockIdx.x * blockDim.x + threadIdx.x;
  if (i < B) atomicMax(&g_owner[nodes[i]], i);  // last-write-wins == max sample index
}

template <int LAYER>
__global__ __launch_bounds__(NT) void layer_kernel(
    const int* __restrict__ nodes, const float* __restrict__ tstamps,
    const int* __restrict__ neighbors, const int* __restrict__ eidx,
    const float* __restrict__ nf, const float* __restrict__ efeat,
    const float* __restrict__ time_w, const float* __restrict__ time_b,
    const float* __restrict__ q_w, const float* __restrict__ k_w,
    const float* __restrict__ v_w, const float* __restrict__ bq,
    const float* __restrict__ bk, const float* __restrict__ bv,
    const float* __restrict__ out_w, const float* __restrict__ out_b,
    float* __restrict__ out) {
  extern __shared__ char smraw[];
  Smem& s = *reinterpret_cast<Smem*>(smraw);
  const int b = blockIdx.x;
  const int tid = threadIdx.x;
  const float tsv = tstamps[b];

  // Per-neighbor source pointers + pad flags
  if (tid < KNB) {
    int nb = neighbors[b * KNB + tid];
    s.pad[tid] = (nb == 0) ? 1 : 0;
    const float* p;
    if (LAYER == 0) {
      p = nf + (size_t)nb * E_;
    } else {
      int ow = g_owner[nb];
      p = (ow >= 0) ? (g_h1 + (size_t)ow * E_) : (nf + (size_t)nb * E_);
    }
    s.nbrp[tid] = p;
    s.efp[tid] = efeat + (size_t)eidx[b * KNB + tid] * DE_;
  }

  // Time encoding + q_in = h + t
  {
    const int node = nodes[b];
    const float* hrow;
    if (LAYER == 0) hrow = nf + (size_t)node * E_;
    else            hrow = g_h1 + (size_t)g_owner[node] * E_;  // owner >= 0 guaranteed (node was scattered)
    for (int e = tid; e < E_; e += NT) {
      // match reference fp32 argument rounding (mul then add), accurate cos
      float arg = __fadd_rn(__fmul_rn(tsv, time_w[e]), time_b[e]);
      float tv = (float)cos((double)arg);
      s.t[e] = tv;
      s.qin[e] = hrow[e] + tv;
    }
  }
  __syncthreads();

  if (tid == 0) {  // invalid-row fixup: if all padded, unmask slot 0
    int all = 1;
#pragma unroll
    for (int j = 0; j < KNB; j++) all &= s.pad[j];
    if (all) s.pad[0] = 0;
  }

  // Gather kv = [hn + t, ef]
  for (int idx = tid; idx < KNB * KVD; idx += NT) {
    int j = idx / KVD, e = idx - j * KVD;
    s.kv[j][e] = (e < E_) ? (s.nbrp[j][e] + s.t[e]) : s.efp[j][e - E_];
  }
  __syncthreads();

  // q projection: q[o] = q_in . q_w[o,:] + bq[o]
  if (tid < E_) {
    const float4* w = reinterpret_cast<const float4*>(q_w + tid * E_);
    const float4* x = reinterpret_cast<const float4*>(s.qin);
    float acc = bq[tid];
#pragma unroll
    for (int c = 0; c < E_ / 4; c++) {
      float4 wv = w[c], xv = x[c];
      acc += wv.x * xv.x + wv.y * xv.y + wv.z * xv.z + wv.w * xv.w;
    }
    s.q[tid] = acc;
  }

  // k/v projection: thread o owns one output row, 20 register accumulators
  if (tid < 2 * E_) {
    const bool isK = (tid < E_);
    const int row = isK ? tid : (tid - E_);
    const float* W = isK ? k_w : v_w;
    float acc[KNB];
    {
      float bias = isK ? bk[row] : bv[row];
#pragma unroll
      for (int j = 0; j < KNB; j++) acc[j] = bias;
    }
    const float4* wr = reinterpret_cast<const float4*>(W + row * KVD);
    for (int c = 0; c < KVD / 8; c++) {  // 43 chunks of 8
      float4 w0 = wr[2 * c], w1 = wr[2 * c + 1];
#pragma unroll
      for (int j = 0; j < KNB; j++) {
        const float4* kvp = reinterpret_cast<const float4*>(&s.kv[j][c * 8]);
        float4 a0 = kvp[0], a1 = kvp[1];
        acc[j] += w0.x * a0.x + w0.y * a0.y + w0.z * a0.z + w0.w * a0.w +
                  w1.x * a1.x + w1.y * a1.y + w1.z * a1.z + w1.w * a1.w;
      }
    }
    float* dstp = isK ? &s.kk[0][0] : &s.vv[0][0];
#pragma unroll
    for (int j = 0; j < KNB; j++) dstp[j * E_ + row] = acc[j];
  }
  __syncthreads();

  // scores[h][j] = (q_h . k_jh) / sqrt(hd), masked
  if (tid < HH * KNB) {
    int h = tid / KNB, j = tid - h * KNB;
    const float* qp = &s.q[h * HD_];
    const float* kp = &s.kk[j][h * HD_];
    float sum = 0.f;
#pragma unroll
    for (int d = 0; d < HD_; d++) sum += qp[d] * kp[d];
    sum *= 0.10783277320343841f;  // 1/sqrt(86)
    if (s.pad[j]) sum = -1e9f;
    s.scores[h][j] = sum;
  }
  __syncthreads();

  // softmax per head
  if (tid < HH) {
    float m = -INFINITY;
#pragma unroll
    for (int j = 0; j < KNB; j++) m = fmaxf(m, s.scores[tid][j]);
    float ex[KNB];
    float ssum = 0.f;
#pragma unroll
    for (int j = 0; j < KNB; j++) { ex[j] = expf(s.scores[tid][j] - m); ssum += ex[j]; }
    float inv = 1.f / ssum;
#pragma unroll
    for (int j = 0; j < KNB; j++) s.attn[tid][j] = ex[j] * inv;
  }
  __syncthreads();

  // out[d] = sum_j attn[h(d)][j] * v[j][d]
  if (tid < E_) {
    int h = tid / HD_;
    float acc = 0.f;
#pragma unroll
    for (int j = 0; j < KNB; j++) acc += s.attn[h][j] * s.vv[j][tid];
    s.outv[tid] = acc;
  }
  __syncthreads();

  // output projection
  if (tid < E_) {
    const float4* w = reinterpret_cast<const float4*>(out_w + tid * E_);
    const float4* x = reinterpret_cast<const float4*>(s.outv);
    float acc = out_b[tid];
#pragma unroll
    for (int c = 0; c < E_ / 4; c++) {
      float4 wv = w[c], xv = x[c];
      acc += wv.x * xv.x + wv.y * xv.y + wv.z * xv.z + wv.w * xv.w;
    }
    float* dst = (LAYER == 0) ? g_h1 : out;
    dst[(size_t)b * E_ + tid] = acc;
  }
}

extern "C" void kernel_launch(void* const* d_in, const int* in_sizes, int n_in,
                              void* d_out, int out_size) {
  const int* nodes      = (const int*)d_in[0];
  const float* ts       = (const float*)d_in[1];
  const int* neighbors  = (const int*)d_in[2];
  const int* eidx       = (const int*)d_in[3];
  const float* nf       = (const float*)d_in[4];
  const float* ef       = (const float*)d_in[5];
  const float* time_w   = (const float*)d_in[6];
  const float* time_b   = (const float*)d_in[7];
  const float* q_w      = (const float*)d_in[8];
  const float* k_w      = (const float*)d_in[9];
  const float* v_w      = (const float*)d_in[10];
  const float* bq       = (const float*)d_in[11];
  const float* bk       = (const float*)d_in[12];
  const float* bv       = (const float*)d_in[13];
  const float* out_w    = (const float*)d_in[14];
  const float* out_b    = (const float*)d_in[15];
  float* out = (float*)d_out;
  const int B = in_sizes[0];

  const int smem = (int)sizeof(Smem);
  cudaFuncSetAttribute(layer_kernel<0>, cudaFuncAttributeMaxDynamicSharedMemorySize, smem);
  cudaFuncSetAttribute(layer_kernel<1>, cudaFuncAttributeMaxDynamicSharedMemorySize, smem);

  init_owner_kernel<<<(NNODES_ + 255) / 256, 256>>>();
  layer_kernel<0><<<B, NT, smem>>>(nodes, ts, neighbors, eidx, nf, ef, time_w, time_b,
                                   q_w, k_w, v_w, bq, bk, bv, out_w, out_b, out);
  build_owner_kernel<<<(B + 255) / 256, 256>>>(nodes, B);
  layer_kernel<1><<<B, NT, smem>>>(nodes, ts, neighbors, eidx, nf, ef, time_w, time_b,
                                   q_w, k_w, v_w, bq, bk, bv, out_w, out_b, out);
}

// round 2
// speedup vs baseline: 2.3744x; 2.3744x over previous
#include <cuda_runtime.h>
#include <math.h>

#define E_ 172
#define KNB 20
#define HH 2
#define HD_ 86
#define NNODES 100000
#define BMAX 12000
#define NSLOTMAX (BMAX * KNB)

// ---------------- scratch (allocation-free: __device__ globals) ----------------
__device__ float g_t[BMAX * E_];             // cos time encoding, per sample
__device__ float g_tqkv[BMAX * 3 * E_];      // [t@q_w^T+bq | t@k_wE^T+bk | t@v_wE^T+bv]
__device__ float g_node_kv[NNODES * 2 * E_]; // per-node [nf@k_wE^T | nf@v_wE^T]
__device__ float g_edge_kv[(size_t)NSLOTMAX * 2 * E_]; // per-slot [ef@k_wD^T | ef@v_wD^T]
__device__ float g_upd_kv[BMAX * 2 * E_];    // layer-1 updated-node [h1@k_wE | h1@v_wE]
__device__ float g_qh[BMAX * E_];            // h @ q_w^T (per layer)
__device__ float g_o[BMAX * E_];             // attention output before out-proj
__device__ float g_h1[BMAX * E_];            // layer-0 output h
__device__ int   g_owner[NNODES];            // last sample writing each node, -1 if none

// ---------------- small kernels ----------------
__global__ void init_owner_kernel() {
  int i = blockIdx.x * blockDim.x + threadIdx.x;
  if (i < NNODES) g_owner[i] = -1;
}
__global__ void build_owner_kernel(const int* __restrict__ nodes, int B) {
  int i = blockIdx.x * blockDim.x + threadIdx.x;
  if (i < B) atomicMax(&g_owner[nodes[i]], i);
}
__global__ void time_kernel(const float* __restrict__ ts, const float* __restrict__ tw,
                            const float* __restrict__ tb, int B) {
  int i = blockIdx.x * blockDim.x + threadIdx.x;
  if (i < B * E_) {
    int b = i / E_, e = i - b * E_;
    float arg = __fadd_rn(__fmul_rn(ts[b], tw[e]), tb[e]);
    g_t[i] = (float)cos((double)arg);
  }
}

// ---------------- tiled GEMM: out[m][n] = sum_c X[src(m)][c] * W(n)[c] (+bias) ----------------
// K fixed = 172. N is split into <=3 segments of 172 columns each (seg = n/172).
// gmode: 0 -> src=m ; 1 -> src=g1[m] ; 2 -> src=g_owner[g1[m]]
struct GArgs {
  const float* w[3];
  int ld[3];
  int coff[3];
  const float* bias[3];
};

#define BMT 64
#define BNT 64
#define TM 8
#define TN 4
#define GT 128
#define NC4 43  // 172/4

struct GemmSmem {
  float Xs[BMT][E_];
  float Ws[BNT][E_];
  int srcrow[BMT];
};

__global__ __launch_bounds__(GT) void gemm_kernel(
    const float* __restrict__ X, const int* __restrict__ g1, int gmode,
    float* __restrict__ out, int M, int N, GArgs a) {
  extern __shared__ char smraw[];
  GemmSmem& s = *reinterpret_cast<GemmSmem*>(smraw);
  const int m0 = blockIdx.x * BMT;
  const int n0 = blockIdx.y * BNT;
  const int tid = threadIdx.x;

  if (tid < BMT) {
    int row = m0 + tid;
    int src = 0;
    if (row < M) {
      src = row;
      if (gmode >= 1) src = g1[row];
      if (gmode == 2) src = g_owner[src];
    }
    s.srcrow[tid] = src;
  }
  __syncthreads();

  // X tile (coalesced float4 rows)
  for (int idx = tid; idx < BMT * NC4; idx += GT) {
    int r = idx / NC4, c4 = idx - r * NC4;
    float4 v = make_float4(0.f, 0.f, 0.f, 0.f);
    if (m0 + r < M)
      v = *reinterpret_cast<const float4*>(X + (size_t)s.srcrow[r] * E_ + c4 * 4);
    *reinterpret_cast<float4*>(&s.Xs[r][c4 * 4]) = v;
  }
  // W tile
  for (int idx = tid; idx < BNT * NC4; idx += GT) {
    int r = idx / NC4, c4 = idx - r * NC4;
    int n = n0 + r;
    float4 v = make_float4(0.f, 0.f, 0.f, 0.f);
    if (n < N) {
      int sg = n / E_;
      int nr = n - sg * E_;
      v = *reinterpret_cast<const float4*>(a.w[sg] + (size_t)nr * a.ld[sg] + a.coff[sg] + c4 * 4);
    }
    *reinterpret_cast<float4*>(&s.Ws[r][c4 * 4]) = v;
  }
  __syncthreads();

  const int tn = tid & 15;
  const int tm = tid >> 4;
  float acc[TM][TN];
#pragma unroll
  for (int i = 0; i < TM; i++)
#pragma unroll
    for (int j = 0; j < TN; j++) acc[i][j] = 0.f;

  for (int c4 = 0; c4 < NC4; c4++) {
    float4 wv[TN];
#pragma unroll
    for (int j = 0; j < TN; j++)
      wv[j] = *reinterpret_cast<const float4*>(&s.Ws[tn + j * 16][c4 * 4]);
#pragma unroll
    for (int i = 0; i < TM; i++) {
      float4 xv = *reinterpret_cast<const float4*>(&s.Xs[tm + i * 8][c4 * 4]);
#pragma unroll
      for (int j = 0; j < TN; j++)
        acc[i][j] += xv.x * wv[j].x + xv.y * wv[j].y + xv.z * wv[j].z + xv.w * wv[j].w;
    }
  }

#pragma unroll
  for (int j = 0; j < TN; j++) {
    int n = n0 + tn + j * 16;
    if (n >= N) continue;
    int sg = n / E_;
    int nr = n - sg * E_;
    float bv = a.bias[sg] ? a.bias[sg][nr] : 0.f;
#pragma unroll
    for (int i = 0; i < TM; i++) {
      int m = m0 + tm + i * 8;
      if (m < M) out[(size_t)m * N + n] = acc[i][j] + bv;
    }
  }
}

// ---------------- attention (per sample) ----------------
template <int LAYER>
__global__ __launch_bounds__(256) void attn_kernel(
    const int* __restrict__ neighbors, int B) {
  __shared__ float q[E_];
  __shared__ float kk[KNB][E_];
  __shared__ float sc[HH][KNB];
  __shared__ float at[HH][KNB];
  __shared__ const float* akp[KNB];
  __shared__ const float* bkp[KNB];
  __shared__ int pad[KNB];

  const int b = blockIdx.x;
  const int tid = threadIdx.x;
  const float* trow = g_tqkv + (size_t)b * (3 * E_);

  if (tid < KNB) {
    int nb = neighbors[b * KNB + tid];
    pad[tid] = (nb == 0) ? 1 : 0;
    const float* ap = g_node_kv + (size_t)nb * (2 * E_);
    if (LAYER == 1) {
      int ow = g_owner[nb];
      if (ow >= 0) ap = g_upd_kv + (size_t)ow * (2 * E_);
    }
    akp[tid] = ap;
    bkp[tid] = g_edge_kv + ((size_t)b * KNB + tid) * (2 * E_);
  }
  if (tid < E_) q[tid] = g_qh[(size_t)b * E_ + tid] + trow[tid];
  __syncthreads();

  // compose k = node_k + edge_k + t_k  (t_k includes bk)
  const float* tk = trow + E_;
  for (int idx = tid; idx < KNB * E_; idx += 256) {
    int j = idx / E_, e = idx - j * E_;
    kk[j][e] = akp[j][e] + bkp[j][e] + tk[e];
  }
  if (tid == 0) {  // invalid-row fixup
    int all = 1;
#pragma unroll
    for (int j = 0; j < KNB; j++) all &= pad[j];
    if (all) pad[0] = 0;
  }
  __syncthreads();

  if (tid < HH * KNB) {
    int h = tid / KNB, j = tid - h * KNB;
    const float* qp = q + h * HD_;
    const float* kp = &kk[j][h * HD_];
    float sum = 0.f;
#pragma unroll
    for (int d = 0; d < HD_; d++) sum += qp[d] * kp[d];
    sum *= 0.10783277320343841f;  // 1/sqrt(86)
    if (pad[j]) sum = -1e9f;
    sc[h][j] = sum;
  }
  __syncthreads();

  if (tid < HH) {
    float m = -INFINITY;
#pragma unroll
    for (int j = 0; j < KNB; j++) m = fmaxf(m, sc[tid][j]);
    float ex[KNB], ssum = 0.f;
#pragma unroll
    for (int j = 0; j < KNB; j++) { ex[j] = expf(sc[tid][j] - m); ssum += ex[j]; }
    float inv = 1.f / ssum;
#pragma unroll
    for (int j = 0; j < KNB; j++) at[tid][j] = ex[j] * inv;
  }
  __syncthreads();

  // out[e] = sum_j attn * (node_v + edge_v) + t_v   (sum attn == 1)
  if (tid < E_) {
    int h = tid / HD_;
    float o = trow[2 * E_ + tid];
#pragma unroll
    for (int j = 0; j < KNB; j++)
      o += at[h][j] * (akp[j][E_ + tid] + bkp[j][E_ + tid]);
    g_o[(size_t)b * E_ + tid] = o;
  }
}

// ---------------- launch ----------------
static inline int cdiv(int a, int b) { return (a + b - 1) / b; }

extern "C" void kernel_launch(void* const* d_in, const int* in_sizes, int n_in,
                              void* d_out, int out_size) {
  const int* nodes     = (const int*)d_in[0];
  const float* ts      = (const float*)d_in[1];
  const int* neighbors = (const int*)d_in[2];
  const int* eidx      = (const int*)d_in[3];
  const float* nf      = (const float*)d_in[4];
  const float* ef      = (const float*)d_in[5];
  const float* time_w  = (const float*)d_in[6];
  const float* time_b  = (const float*)d_in[7];
  const float* q_w     = (const float*)d_in[8];
  const float* k_w     = (const float*)d_in[9];
  const float* v_w     = (const float*)d_in[10];
  const float* bq      = (const float*)d_in[11];
  const float* bk      = (const float*)d_in[12];
  const float* bv      = (const float*)d_in[13];
  const float* out_w   = (const float*)d_in[14];
  const float* out_b   = (const float*)d_in[15];
  float* out = (float*)d_out;
  const int B = in_sizes[0];
  const int NSLOT = B * KNB;

  float *p_t, *p_tqkv, *p_nodekv, *p_edgekv, *p_updkv, *p_qh, *p_o, *p_h1;
  cudaGetSymbolAddress((void**)&p_t, g_t);
  cudaGetSymbolAddress((void**)&p_tqkv, g_tqkv);
  cudaGetSymbolAddress((void**)&p_nodekv, g_node_kv);
  cudaGetSymbolAddress((void**)&p_edgekv, g_edge_kv);
  cudaGetSymbolAddress((void**)&p_updkv, g_upd_kv);
  cudaGetSymbolAddress((void**)&p_qh, g_qh);
  cudaGetSymbolAddress((void**)&p_o, g_o);
  cudaGetSymbolAddress((void**)&p_h1, g_h1);

  const int smem = (int)sizeof(GemmSmem);
  cudaFuncSetAttribute(gemm_kernel, cudaFuncAttributeMaxDynamicSharedMemorySize, smem);

  init_owner_kernel<<<cdiv(NNODES, 256), 256>>>();
  time_kernel<<<cdiv(B * E_, 256), 256>>>(ts, time_w, time_b, B);

  GArgs a;
  // t -> [q|k|v] projections (+bias), N=516
  a.w[0] = q_w; a.ld[0] = E_;     a.coff[0] = 0; a.bias[0] = bq;
  a.w[1] = k_w; a.ld[1] = 2 * E_; a.coff[1] = 0; a.bias[1] = bk;
  a.w[2] = v_w; a.ld[2] = 2 * E_; a.coff[2] = 0; a.bias[2] = bv;
  gemm_kernel<<<dim3(cdiv(B, BMT), cdiv(3 * E_, BNT)), GT, smem>>>(
      p_t, nullptr, 0, p_tqkv, B, 3 * E_, a);

  // nf -> node [k|v], N=344 (first-172-col slices of k_w/v_w)
  a.w[0] = k_w; a.ld[0] = 2 * E_; a.coff[0] = 0; a.bias[0] = nullptr;
  a.w[1] = v_w; a.ld[1] = 2 * E_; a.coff[1] = 0; a.bias[1] = nullptr;
  a.w[2] = nullptr; a.ld[2] = 0; a.coff[2] = 0; a.bias[2] = nullptr;
  gemm_kernel<<<dim3(cdiv(NNODES, BMT), cdiv(2 * E_, BNT)), GT, smem>>>(
      nf, nullptr, 0, p_nodekv, NNODES, 2 * E_, a);

  // gathered ef -> edge [k|v], N=344 (last-172-col slices), layer-invariant
  a.w[0] = k_w; a.ld[0] = 2 * E_; a.coff[0] = E_; a.bias[0] = nullptr;
  a.w[1] = v_w; a.ld[1] = 2 * E_; a.coff[1] = E_; a.bias[1] = nullptr;
  gemm_kernel<<<dim3(cdiv(NSLOT, BMT), cdiv(2 * E_, BNT)), GT, smem>>>(
      ef, eidx, 1, p_edgekv, NSLOT, 2 * E_, a);

  // ---- layer 0 ----
  GArgs aq;
  aq.w[0] = q_w; aq.ld[0] = E_; aq.coff[0] = 0; aq.bias[0] = nullptr;
  aq.w[1] = nullptr; aq.ld[1] = 0; aq.coff[1] = 0; aq.bias[1] = nullptr;
  aq.w[2] = nullptr; aq.ld[2] = 0; aq.coff[2] = 0; aq.bias[2] = nullptr;
  gemm_kernel<<<dim3(cdiv(B, BMT), cdiv(E_, BNT)), GT, smem>>>(
      nf, nodes, 1, p_qh, B, E_, aq);

  attn_kernel<0><<<B, 256>>>(neighbors, B);

  GArgs ao;
  ao.w[0] = out_w; ao.ld[0] = E_; ao.coff[0] = 0; ao.bias[0] = out_b;
  ao.w[1] = nullptr; ao.ld[1] = 0; ao.coff[1] = 0; ao.bias[1] = nullptr;
  ao.w[2] = nullptr; ao.ld[2] = 0; ao.coff[2] = 0; ao.bias[2] = nullptr;
  gemm_kernel<<<dim3(cdiv(B, BMT), cdiv(E_, BNT)), GT, smem>>>(
      p_o, nullptr, 0, p_h1, B, E_, ao);

  build_owner_kernel<<<cdiv(B, 256), 256>>>(nodes, B);

  // ---- layer 1 ----
  // q: gather h1[owner[nodes[b]]] @ q_w^T
  gemm_kernel<<<dim3(cdiv(B, BMT), cdiv(E_, BNT)), GT, smem>>>(
      p_h1, nodes, 2, p_qh, B, E_, aq);

  // updated-node kv: h1 @ [k_wE|v_wE]^T
  a.w[0] = k_w; a.ld[0] = 2 * E_; a.coff[0] = 0; a.bias[0] = nullptr;
  a.w[1] = v_w; a.ld[1] = 2 * E_; a.coff[1] = 0; a.bias[1] = nullptr;
  gemm_kernel<<<dim3(cdiv(B, BMT), cdiv(2 * E_, BNT)), GT, smem>>>(
      p_h1, nullptr, 0, p_updkv, B, 2 * E_, a);

  attn_kernel<1><<<B, 256>>>(neighbors, B);

  gemm_kernel<<<dim3(cdiv(B, BMT), cdiv(E_, BNT)), GT, smem>>>(
      p_o, nullptr, 0, out, B, E_, ao);
}

// round 3
// speedup vs baseline: 6.0229x; 2.5366x over previous
#include <cuda_runtime.h>
#include <cuda_bf16.h>
#include <math.h>
#include <stdint.h>

#define E_ 172
#define KP 192            // padded K
#define KNB 20
#define HH 2
#define HD_ 86
#define NNODES 100000
#define BMAX 12000
#define BPAD 12032        // ceil(12000/128)*128
#define NPADN 100096      // ceil(100000/128)*128
#define NSLOT 240000      // BMAX*KNB (divisible by 128)

// pack row offsets within the packed weight buffer
#define P1_OFF 0      // tqkv: 3 segs (q,kE,vE) + biases        N=576
#define P2_OFF 576    // node/upd kv: (kE, vE)                  N=384
#define P3_OFF 960    // edge kv: (kD, vD)                      N=384
#define P4_OFF 1344   // q proj                                 N=192
#define P5_OFF 1536   // out proj + bias                        N=192
#define PTOT 1728

// ---------------- scratch ----------------
__device__ __nv_bfloat16 g_Ahi[(size_t)NSLOT * KP];
__device__ __nv_bfloat16 g_Alo[(size_t)NSLOT * KP];
__device__ __nv_bfloat16 g_Whi[PTOT * KP];
__device__ __nv_bfloat16 g_Wlo[PTOT * KP];
__device__ float g_Wb[PTOT];

__device__ float g_tqkv[BMAX * 576];               // [tq | tk | tv] (biases folded)
__device__ float g_node_kv[(size_t)NNODES * 384];  // [k | v] per node
__device__ float g_edge_kv[(size_t)NSLOT * 384];   // [k | v] per slot
__device__ float g_upd_kv[BMAX * 384];
__device__ float g_qh[BMAX * KP];
__device__ float g_o[BMAX * KP];
__device__ float g_h1[BMAX * KP];
__device__ int   g_owner[NNODES];

// ---------------- helpers ----------------
__device__ __forceinline__ void bf16split(float v, __nv_bfloat16& h, __nv_bfloat16& l) {
  h = __float2bfloat16(v);
  l = __float2bfloat16(v - __bfloat162float(h));
}

__global__ void init_owner_kernel() {
  int i = blockIdx.x * blockDim.x + threadIdx.x;
  if (i < NNODES) g_owner[i] = -1;
}
__global__ void build_owner_kernel(const int* __restrict__ nodes, int B) {
  int i = blockIdx.x * blockDim.x + threadIdx.x;
  if (i < B) atomicMax(&g_owner[nodes[i]], i);
}

// ---------------- weight packing ----------------
struct PArgs {
  const float* w[3];
  int ld[3];
  int coff[3];
  const float* bias[3];
};
__global__ void pack_w_kernel(PArgs a, int nseg, __nv_bfloat16* whi,
                              __nv_bfloat16* wlo, float* pbias) {
  int i = blockIdx.x * blockDim.x + threadIdx.x;
  int tot = nseg * KP * KP;
  if (i >= tot) return;
  int n = i / KP, c = i - n * KP;
  int seg = n / KP, nr = n - seg * KP;
  float v = 0.f;
  if (nr < E_ && c < E_) v = a.w[seg][(size_t)nr * a.ld[seg] + a.coff[seg] + c];
  __nv_bfloat16 h, l;
  bf16split(v, h, l);
  whi[i] = h; wlo[i] = l;
  if (c == 0) pbias[n] = (nr < E_ && a.bias[seg]) ? a.bias[seg][nr] : 0.f;
}

// ---------------- input conversion (optional gather) ----------------
// gmode: 0 src=r ; 1 src=g1[r] ; 2 src=owner[g1[r]]
__global__ void convert_kernel(const float* __restrict__ X, int ldx,
                               const int* __restrict__ g1, int gmode,
                               int M, int Mpad) {
  int i = blockIdx.x * blockDim.x + threadIdx.x;
  if (i >= Mpad * KP) return;
  int r = i / KP, c = i - r * KP;
  float v = 0.f;
  if (r < M && c < E_) {
    int src = r;
    if (gmode >= 1) src = g1[r];
    if (gmode == 2) src = g_owner[src];
    v = X[(size_t)src * ldx + c];
  }
  __nv_bfloat16 h, l;
  bf16split(v, h, l);
  g_Ahi[i] = h; g_Alo[i] = l;
}

__global__ void timeconv_kernel(const float* __restrict__ ts,
                                const float* __restrict__ tw,
                                const float* __restrict__ tb, int B, int Mpad) {
  int i = blockIdx.x * blockDim.x + threadIdx.x;
  if (i >= Mpad * KP) return;
  int r = i / KP, c = i - r * KP;
  float v = 0.f;
  if (r < B && c < E_) {
    float arg = __fadd_rn(__fmul_rn(ts[r], tw[c]), tb[c]);
    v = (float)cos((double)arg);
  }
  __nv_bfloat16 h, l;
  bf16split(v, h, l);
  g_Ahi[i] = h; g_Alo[i] = l;
}

// ---------------- tensor-core GEMM ----------------
#define GBM 128
#define GBN 96
#define GSTR 72  // smem row stride in halves (conflict-free for ldmatrix)
#define SMEM_GEMM ((2 * GBM * GSTR + 2 * GBN * GSTR) * 2)

__device__ __forceinline__ void ldsm4(uint32_t* r, uint32_t addr) {
  asm volatile("ldmatrix.sync.aligned.m8n8.x4.shared.b16 {%0,%1,%2,%3}, [%4];"
               : "=r"(r[0]), "=r"(r[1]), "=r"(r[2]), "=r"(r[3]) : "r"(addr));
}
__device__ __forceinline__ void mma_bf16(float* d, const uint32_t* a, const uint32_t* b) {
  asm volatile(
      "mma.sync.aligned.m16n8k16.row.col.f32.bf16.bf16.f32 "
      "{%0,%1,%2,%3},{%4,%5,%6,%7},{%8,%9},{%0,%1,%2,%3};"
      : "+f"(d[0]), "+f"(d[1]), "+f"(d[2]), "+f"(d[3])
      : "r"(a[0]), "r"(a[1]), "r"(a[2]), "r"(a[3]), "r"(b[0]), "r"(b[1]));
}

__global__ __launch_bounds__(256, 2) void mma_gemm_kernel(
    const __nv_bfloat16* __restrict__ Ahi, const __nv_bfloat16* __restrict__ Alo,
    const __nv_bfloat16* __restrict__ Whi, const __nv_bfloat16* __restrict__ Wlo,
    const float* __restrict__ bias, float* __restrict__ out,
    int M, int ldout, int segstride, int nwrite) {
  extern __shared__ __align__(16) char smraw[];
  __nv_bfloat16* sAh = (__nv_bfloat16*)smraw;
  __nv_bfloat16* sAl = sAh + GBM * GSTR;
  __nv_bfloat16* sWh = sAl + GBM * GSTR;
  __nv_bfloat16* sWl = sWh + GBN * GSTR;

  const int tid = threadIdx.x;
  const int warp = tid >> 5, lane = tid & 31;
  const int m0 = blockIdx.x * GBM;
  const int n0 = blockIdx.y * GBN;
  const int wm0 = (warp >> 1) * 32;
  const int wn0 = (warp & 1) * 48;

  float acc[2][6][4];
#pragma unroll
  for (int i = 0; i < 2; i++)
#pragma unroll
    for (int j = 0; j < 6; j++)
#pragma unroll
      for (int k = 0; k < 4; k++) acc[i][j][k] = 0.f;

  const int aRow = (lane & 7) + ((lane >> 3) & 1) * 8;
  const int aCol = ((lane >> 4) & 1) * 8;
  const int bRow = (lane & 7) + ((lane >> 4) & 1) * 8;
  const int bCol = ((lane >> 3) & 1) * 8;

  const uint32_t sAhB = (uint32_t)__cvta_generic_to_shared(sAh);
  const uint32_t sAlB = (uint32_t)__cvta_generic_to_shared(sAl);
  const uint32_t sWhB = (uint32_t)__cvta_generic_to_shared(sWh);
  const uint32_t sWlB = (uint32_t)__cvta_generic_to_shared(sWl);

  for (int kc = 0; kc < 3; kc++) {
    const int c0 = kc * 64;
#pragma unroll
    for (int it = 0; it < 4; it++) {
      int idx = tid + it * 256;  // 1024 float4 per A buffer
      int r = idx >> 3, c8 = idx & 7;
      size_t goff = (size_t)(m0 + r) * KP + c0 + c8 * 8;
      int soff = r * GSTR + c8 * 8;
      *(float4*)(sAh + soff) = *(const float4*)(Ahi + goff);
      *(float4*)(sAl + soff) = *(const float4*)(Alo + goff);
    }
#pragma unroll
    for (int it = 0; it < 3; it++) {
      int idx = tid + it * 256;  // 768 float4 per W buffer
      int r = idx >> 3, c8 = idx & 7;
      size_t goff = (size_t)(n0 + r) * KP + c0 + c8 * 8;
      int soff = r * GSTR + c8 * 8;
      *(float4*)(sWh + soff) = *(const float4*)(Whi + goff);
      *(float4*)(sWl + soff) = *(const float4*)(Wlo + goff);
    }
    __syncthreads();

#pragma unroll
    for (int k16 = 0; k16 < 4; k16++) {
      const int kb = k16 * 16;
      uint32_t ah[2][4], al[2][4], bh[6][2], bl[6][2];
#pragma unroll
      for (int ti = 0; ti < 2; ti++) {
        uint32_t off = (uint32_t)(((wm0 + ti * 16 + aRow) * GSTR + kb + aCol) * 2);
        ldsm4(ah[ti], sAhB + off);
        ldsm4(al[ti], sAlB + off);
      }
#pragma unroll
      for (int p = 0; p < 3; p++) {
        uint32_t off = (uint32_t)(((wn0 + p * 16 + bRow) * GSTR + kb + bCol) * 2);
        uint32_t t[4];
        ldsm4(t, sWhB + off);
        bh[2 * p][0] = t[0]; bh[2 * p][1] = t[1];
        bh[2 * p + 1][0] = t[2]; bh[2 * p + 1][1] = t[3];
        ldsm4(t, sWlB + off);
        bl[2 * p][0] = t[0]; bl[2 * p][1] = t[1];
        bl[2 * p + 1][0] = t[2]; bl[2 * p + 1][1] = t[3];
      }
#pragma unroll
      for (int ti = 0; ti < 2; ti++)
#pragma unroll
        for (int nj = 0; nj < 6; nj++) {
          mma_bf16(acc[ti][nj], ah[ti], bh[nj]);
          mma_bf16(acc[ti][nj], ah[ti], bl[nj]);
          mma_bf16(acc[ti][nj], al[ti], bh[nj]);
        }
    }
    __syncthreads();
  }

  // epilogue
  const int g = lane >> 2, tq = lane & 3;
#pragma unroll
  for (int ti = 0; ti < 2; ti++) {
    int m = m0 + wm0 + ti * 16 + g;
#pragma unroll
    for (int nj = 0; nj < 6; nj++) {
      int n = n0 + wn0 + nj * 8 + tq * 2;
      int seg = n / KP, nr = n - seg * KP;
      if (nr >= nwrite) continue;
      int col = seg * segstride + nr;
      float b0 = bias[n], b1 = bias[n + 1];
      if (m < M)
        *(float2*)(out + (size_t)m * ldout + col) =
            make_float2(acc[ti][nj][0] + b0, acc[ti][nj][1] + b1);
      if (m + 8 < M)
        *(float2*)(out + (size_t)(m + 8) * ldout + col) =
            make_float2(acc[ti][nj][2] + b0, acc[ti][nj][3] + b1);
    }
  }
}

// ---------------- attention (per sample) ----------------
template <int LAYER>
__global__ __launch_bounds__(256) void attn_kernel(const int* __restrict__ neighbors, int B) {
  __shared__ float q[E_];
  __shared__ float kk[KNB][E_];
  __shared__ float sc[HH][KNB];
  __shared__ float at[HH][KNB];
  __shared__ const float* akp[KNB];
  __shared__ const float* bkp[KNB];
  __shared__ int pad[KNB];

  const int b = blockIdx.x;
  const int tid = threadIdx.x;
  const float* trow = g_tqkv + (size_t)b * 576;

  if (tid < KNB) {
    int nb = neighbors[b * KNB + tid];
    pad[tid] = (nb == 0) ? 1 : 0;
    const float* ap = g_node_kv + (size_t)nb * 384;
    if (LAYER == 1) {
      int ow = g_owner[nb];
      if (ow >= 0) ap = g_upd_kv + (size_t)ow * 384;
    }
    akp[tid] = ap;
    bkp[tid] = g_edge_kv + ((size_t)b * KNB + tid) * 384;
  }
  if (tid < E_) q[tid] = g_qh[(size_t)b * KP + tid] + trow[tid];
  __syncthreads();

  const float* tk = trow + 192;
  for (int idx = tid; idx < KNB * E_; idx += 256) {
    int j = idx / E_, e = idx - j * E_;
    kk[j][e] = akp[j][e] + bkp[j][e] + tk[e];
  }
  if (tid == 0) {
    int all = 1;
#pragma unroll
    for (int j = 0; j < KNB; j++) all &= pad[j];
    if (all) pad[0] = 0;
  }
  __syncthreads();

  if (tid < HH * KNB) {
    int h = tid / KNB, j = tid - h * KNB;
    const float* qp = q + h * HD_;
    const float* kp = &kk[j][h * HD_];
    float sum = 0.f;
#pragma unroll
    for (int d = 0; d < HD_; d++) sum += qp[d] * kp[d];
    sum *= 0.10783277320343841f;
    if (pad[j]) sum = -1e9f;
    sc[h][j] = sum;
  }
  __syncthreads();

  if (tid < HH) {
    float m = -INFINITY;
#pragma unroll
    for (int j = 0; j < KNB; j++) m = fmaxf(m, sc[tid][j]);
    float ex[KNB], ssum = 0.f;
#pragma unroll
    for (int j = 0; j < KNB; j++) { ex[j] = expf(sc[tid][j] - m); ssum += ex[j]; }
    float inv = 1.f / ssum;
#pragma unroll
    for (int j = 0; j < KNB; j++) at[tid][j] = ex[j] * inv;
  }
  __syncthreads();

  if (tid < E_) {
    int h = tid / HD_;
    float o = trow[384 + tid];  // t_v (includes bv); sum(attn)==1
#pragma unroll
    for (int j = 0; j < KNB; j++)
      o += at[h][j] * (akp[j][192 + tid] + bkp[j][192 + tid]);
    g_o[(size_t)b * KP + tid] = o;
  }
}

// ---------------- launch ----------------
static inline int cdiv(int a, int b) { return (a + b - 1) / b; }

extern "C" void kernel_launch(void* const* d_in, const int* in_sizes, int n_in,
                              void* d_out, int out_size) {
  const int* nodes     = (const int*)d_in[0];
  const float* ts      = (const float*)d_in[1];
  const int* neighbors = (const int*)d_in[2];
  const int* eidx      = (const int*)d_in[3];
  const float* nf      = (const float*)d_in[4];
  const float* ef      = (const float*)d_in[5];
  const float* time_w  = (const float*)d_in[6];
  const float* time_b  = (const float*)d_in[7];
  const float* q_w     = (const float*)d_in[8];
  const float* k_w     = (const float*)d_in[9];
  const float* v_w     = (const float*)d_in[10];
  const float* bq      = (const float*)d_in[11];
  const float* bk      = (const float*)d_in[12];
  const float* bv      = (const float*)d_in[13];
  const float* out_w   = (const float*)d_in[14];
  const float* out_b   = (const float*)d_in[15];
  float* out = (float*)d_out;
  const int B = in_sizes[0];

  __nv_bfloat16 *pWhi, *pWlo;
  float *pWb, *ptqkv, *pnodekv, *pedgekv, *pupdkv, *pqh, *po, *ph1;
  cudaGetSymbolAddress((void**)&pWhi, g_Whi);
  cudaGetSymbolAddress((void**)&pWlo, g_Wlo);
  cudaGetSymbolAddress((void**)&pWb, g_Wb);
  cudaGetSymbolAddress((void**)&ptqkv, g_tqkv);
  cudaGetSymbolAddress((void**)&pnodekv, g_node_kv);
  cudaGetSymbolAddress((void**)&pedgekv, g_edge_kv);
  cudaGetSymbolAddress((void**)&pupdkv, g_upd_kv);
  cudaGetSymbolAddress((void**)&pqh, g_qh);
  cudaGetSymbolAddress((void**)&po, g_o);
  cudaGetSymbolAddress((void**)&ph1, g_h1);

  cudaFuncSetAttribute(mma_gemm_kernel, cudaFuncAttributeMaxDynamicSharedMemorySize, SMEM_GEMM);

  init_owner_kernel<<<cdiv(NNODES, 256), 256>>>();

  // ---- weight packs ----
  PArgs p;
  p.w[0] = q_w; p.ld[0] = E_;     p.coff[0] = 0;  p.bias[0] = bq;
  p.w[1] = k_w; p.ld[1] = 2 * E_; p.coff[1] = 0;  p.bias[1] = bk;
  p.w[2] = v_w; p.ld[2] = 2 * E_; p.coff[2] = 0;  p.bias[2] = bv;
  pack_w_kernel<<<cdiv(3 * KP * KP, 256), 256>>>(p, 3, pWhi + (size_t)P1_OFF * KP, pWlo + (size_t)P1_OFF * KP, pWb + P1_OFF);
  p.bias[0] = nullptr; p.bias[1] = nullptr; p.bias[2] = nullptr;
  p.w[0] = k_w; p.ld[0] = 2 * E_; p.coff[0] = 0;
  p.w[1] = v_w; p.ld[1] = 2 * E_; p.coff[1] = 0;
  pack_w_kernel<<<cdiv(2 * KP * KP, 256), 256>>>(p, 2, pWhi + (size_t)P2_OFF * KP, pWlo + (size_t)P2_OFF * KP, pWb + P2_OFF);
  p.coff[0] = E_; p.coff[1] = E_;
  pack_w_kernel<<<cdiv(2 * KP * KP, 256), 256>>>(p, 2, pWhi + (size_t)P3_OFF * KP, pWlo + (size_t)P3_OFF * KP, pWb + P3_OFF);
  p.w[0] = q_w; p.ld[0] = E_; p.coff[0] = 0;
  pack_w_kernel<<<cdiv(KP * KP, 256), 256>>>(p, 1, pWhi + (size_t)P4_OFF * KP, pWlo + (size_t)P4_OFF * KP, pWb + P4_OFF);
  p.w[0] = out_w; p.bias[0] = out_b;
  pack_w_kernel<<<cdiv(KP * KP, 256), 256>>>(p, 1, pWhi + (size_t)P5_OFF * KP, pWlo + (size_t)P5_OFF * KP, pWb + P5_OFF);

  __nv_bfloat16 *pAhi, *pAlo;
  cudaGetSymbolAddress((void**)&pAhi, g_Ahi);
  cudaGetSymbolAddress((void**)&pAlo, g_Alo);

#define GEMM(Mpad, Npad, poff, outp, M, ldo, segs, nw)                              \
  mma_gemm_kernel<<<dim3((Mpad) / GBM, (Npad) / GBN), 256, SMEM_GEMM>>>(            \
      pAhi, pAlo, pWhi + (size_t)(poff) * KP, pWlo + (size_t)(poff) * KP,           \
      pWb + (poff), outp, M, ldo, segs, nw)

  // t -> tqkv
  timeconv_kernel<<<cdiv(BPAD * KP, 256), 256>>>(ts, time_w, time_b, B, BPAD);
  GEMM(BPAD, 576, P1_OFF, ptqkv, B, 576, KP, KP);

  // nf -> node kv
  convert_kernel<<<cdiv(NPADN * KP, 256), 256>>>(nf, E_, nullptr, 0, NNODES, NPADN);
  GEMM(NPADN, 384, P2_OFF, pnodekv, NNODES, 384, KP, KP);

  // gathered ef -> edge kv
  convert_kernel<<<cdiv(NSLOT * KP, 256), 256>>>(ef, E_, eidx, 1, B * KNB, NSLOT);
  GEMM(NSLOT, 384, P3_OFF, pedgekv, B * KNB, 384, KP, KP);

  // ---- layer 0 ----
  convert_kernel<<<cdiv(BPAD * KP, 256), 256>>>(nf, E_, nodes, 1, B, BPAD);
  GEMM(BPAD, KP, P4_OFF, pqh, B, KP, KP, KP);

  attn_kernel<0><<<B, 256>>>(neighbors, B);

  convert_kernel<<<cdiv(BPAD * KP, 256), 256>>>(po, KP, nullptr, 0, B, BPAD);
  GEMM(BPAD, KP, P5_OFF, ph1, B, KP, KP, KP);

  build_owner_kernel<<<cdiv(B, 256), 256>>>(nodes, B);

  // ---- layer 1 ----
  convert_kernel<<<cdiv(BPAD * KP, 256), 256>>>(ph1, KP, nodes, 2, B, BPAD);
  GEMM(BPAD, KP, P4_OFF, pqh, B, KP, KP, KP);

  convert_kernel<<<cdiv(BPAD * KP, 256), 256>>>(ph1, KP, nullptr, 0, B, BPAD);
  GEMM(BPAD, 384, P2_OFF, pupdkv, B, 384, KP, KP);

  attn_kernel<1><<<B, 256>>>(neighbors, B);

  convert_kernel<<<cdiv(BPAD * KP, 256), 256>>>(po, KP, nullptr, 0, B, BPAD);
  GEMM(BPAD, KP, P5_OFF, out, B, E_, 0, E_);
#undef GEMM
}

// round 5
// speedup vs baseline: 6.5504x; 1.0876x over previous
#include <cuda_runtime.h>
#include <cuda_bf16.h>
#include <math.h>
#include <stdint.h>

#define E_ 172
#define KP 176            // padded K (11 k16 steps)
#define KSTEPS 11
#define NSEG 192          // padded N per weight segment
#define KNB 20
#define HH 2
#define HD_ 86
#define NNODES 100000
#define BMAX 12000
#define BPAD 12032        // 94*128
#define NPADN 100096      // 782*128
#define NSLOT 240000      // 1875*128

// pack row offsets within the packed weight buffer (rows of KP cols)
#define P1_OFF 0      // tqkv: 3 segs (q,kE,vE) + biases        N=576
#define P2_OFF 576    // node/upd kv: (kE, vE)                  N=384
#define P3_OFF 960    // edge kv: (kD, vD)                      N=384
#define P4_OFF 1344   // q proj                                 N=192
#define P5_OFF 1536   // out proj + bias                        N=192
#define PTOT 1728
#define PPAD (PTOT + 128)

// ---------------- scratch ----------------
__device__ __nv_bfloat16 g_Ahi[(size_t)NSLOT * KP];
__device__ __nv_bfloat16 g_Alo[(size_t)NSLOT * KP];
__device__ __nv_bfloat16 g_Whi[(size_t)PPAD * KP];
__device__ __nv_bfloat16 g_Wlo[(size_t)PPAD * KP];
__device__ float g_Wb[PPAD];

__device__ float g_tqkv[BMAX * 576];
__device__ float g_node_kv[(size_t)NNODES * 384];
__device__ float g_edge_kv[(size_t)NSLOT * 384];
__device__ float g_upd_kv[BMAX * 384];
__device__ float g_qh[BMAX * KP];
__device__ float g_o[BMAX * KP];
__device__ float g_h1[BMAX * KP];
__device__ int   g_owner[NNODES];

// ---------------- helpers ----------------
__device__ __forceinline__ void cpa16(uint32_t dst, const void* src) {
  asm volatile("cp.async.cg.shared.global [%0], [%1], 16;" :: "r"(dst), "l"(src));
}
__device__ __forceinline__ void cpa_commit() { asm volatile("cp.async.commit_group;" ::: "memory"); }
template <int N>
__device__ __forceinline__ void cpa_wait() { asm volatile("cp.async.wait_group %0;" :: "n"(N) : "memory"); }

__device__ __forceinline__ void ldsm4(uint32_t* r, uint32_t addr) {
  asm volatile("ldmatrix.sync.aligned.m8n8.x4.shared.b16 {%0,%1,%2,%3}, [%4];"
               : "=r"(r[0]), "=r"(r[1]), "=r"(r[2]), "=r"(r[3]) : "r"(addr));
}
__device__ __forceinline__ void mma_bf16(float* d, const uint32_t* a, const uint32_t* b) {
  asm volatile(
      "mma.sync.aligned.m16n8k16.row.col.f32.bf16.bf16.f32 "
      "{%0,%1,%2,%3},{%4,%5,%6,%7},{%8,%9},{%0,%1,%2,%3};"
      : "+f"(d[0]), "+f"(d[1]), "+f"(d[2]), "+f"(d[3])
      : "r"(a[0]), "r"(a[1]), "r"(a[2]), "r"(a[3]), "r"(b[0]), "r"(b[1]));
}

__device__ __forceinline__ void bf16split(float v, __nv_bfloat16& h, __nv_bfloat16& l) {
  h = __float2bfloat16(v);
  l = __float2bfloat16(v - __bfloat162float(h));
}

// ---------------- small kernels ----------------
__global__ void init_owner_kernel() {
  int i = blockIdx.x * blockDim.x + threadIdx.x;
  if (i < NNODES) g_owner[i] = -1;
}
__global__ void build_owner_kernel(const int* __restrict__ nodes, int B) {
  int i = blockIdx.x * blockDim.x + threadIdx.x;
  if (i < B) atomicMax(&g_owner[nodes[i]], i);
}

// ---------------- weight packing ----------------
struct PArgs {
  const float* w[3];
  int ld[3];
  int coff[3];
  const float* bias[3];
};
__global__ void pack_w_kernel(PArgs a, int nseg, __nv_bfloat16* whi,
                              __nv_bfloat16* wlo, float* pbias) {
  int i = blockIdx.x * blockDim.x + threadIdx.x;
  int tot = nseg * NSEG * KP;
  if (i >= tot) return;
  int n = i / KP, c = i - n * KP;
  int seg = n / NSEG, nr = n - seg * NSEG;
  float v = 0.f;
  if (nr < E_ && c < E_) v = a.w[seg][(size_t)nr * a.ld[seg] + a.coff[seg] + c];
  __nv_bfloat16 h, l;
  bf16split(v, h, l);
  whi[i] = h; wlo[i] = l;
  if (c == 0) pbias[n] = (nr < E_ && a.bias[seg]) ? a.bias[seg][nr] : 0.f;
}

// ---------------- input conversion (optional gather) ----------------
__global__ void convert_kernel(const float* __restrict__ X, int ldx,
                               const int* __restrict__ g1, int gmode,
                               int M, int Mpad) {
  int i = blockIdx.x * blockDim.x + threadIdx.x;
  if (i >= Mpad * KP) return;
  int r = i / KP, c = i - r * KP;
  float v = 0.f;
  if (r < M && c < E_) {
    int src = r;
    if (gmode >= 1) src = g1[r];
    if (gmode == 2) src = g_owner[src];
    v = X[(size_t)src * ldx + c];
  }
  __nv_bfloat16 h, l;
  bf16split(v, h, l);
  g_Ahi[i] = h; g_Alo[i] = l;
}

__global__ void timeconv_kernel(const float* __restrict__ ts,
                                const float* __restrict__ tw,
                                const float* __restrict__ tb, int B, int Mpad) {
  int i = blockIdx.x * blockDim.x + threadIdx.x;
  if (i >= Mpad * KP) return;
  int r = i / KP, c = i - r * KP;
  float v = 0.f;
  if (r < B && c < E_) {
    float arg = __fadd_rn(__fmul_rn(ts[r], tw[c]), tb[c]);
    v = (float)cos((double)arg);
  }
  __nv_bfloat16 h, l;
  bf16split(v, h, l);
  g_Ahi[i] = h; g_Alo[i] = l;
}

// ---------------- pipelined bf16 HMMA GEMM ----------------
// Tile 128(M) x 96(N), K pipelined in 16-col stages (4-stage cp.async ring).
#define BM 128
#define BN 96
#define ST 24                    // smem row stride in halves (conflict-free LDSM)
#define STAGE_A_B (BM * ST * 2)  // 6144 bytes per A stage
#define STAGE_B_B (BN * ST * 2)  // 4608 bytes per B stage
#define SM_AH 0
#define SM_AL (SM_AH + 4 * STAGE_A_B)
#define SM_BH (SM_AL + 4 * STAGE_A_B)
#define SM_BL (SM_BH + 4 * STAGE_B_B)
#define SMEM_G (SM_BL + 4 * STAGE_B_B)  // 86016 bytes

__global__ __launch_bounds__(256, 2) void mma_gemm_kernel(
    const __nv_bfloat16* __restrict__ Ahi, const __nv_bfloat16* __restrict__ Alo,
    const __nv_bfloat16* __restrict__ Whi, const __nv_bfloat16* __restrict__ Wlo,
    const float* __restrict__ bias, float* __restrict__ out,
    int M, int ldout, int segstride, int nwrite) {
  extern __shared__ __align__(128) char smraw[];
  const uint32_t sm = (uint32_t)__cvta_generic_to_shared(smraw);
  const int tid = threadIdx.x;
  const int warp = tid >> 5, lane = tid & 31;
  const int m0 = blockIdx.y * BM;
  const int n0 = blockIdx.x * BN;
  const int wm0 = (warp >> 1) * 32;
  const int wn0 = (warp & 1) * 48;

  float acc[2][6][4];
#pragma unroll
  for (int i = 0; i < 2; i++)
#pragma unroll
    for (int j = 0; j < 6; j++)
#pragma unroll
      for (int k = 0; k < 4; k++) acc[i][j][k] = 0.f;

  // per-thread load slots
  const int lr = tid >> 1, lch = tid & 1;
  const size_t srcA = (size_t)(m0 + lr) * KP + lch * 8;
  const size_t srcB = (size_t)(n0 + lr) * KP + lch * 8;
  const uint32_t dstAoff = (uint32_t)((lr * ST + lch * 8) * 2);
  const uint32_t dstBoff = dstAoff;  // same formula, region differs

#define LOAD_STAGE(buf, ki)                                                   \
  do {                                                                        \
    cpa16(sm + SM_AH + (buf) * STAGE_A_B + dstAoff, Ahi + srcA + (ki) * 16);  \
    cpa16(sm + SM_AL + (buf) * STAGE_A_B + dstAoff, Alo + srcA + (ki) * 16);  \
    if (tid < 2 * BN) {                                                       \
      cpa16(sm + SM_BH + (buf) * STAGE_B_B + dstBoff, Whi + srcB + (ki) * 16);\
      cpa16(sm + SM_BL + (buf) * STAGE_B_B + dstBoff, Wlo + srcB + (ki) * 16);\
    }                                                                         \
  } while (0)

  LOAD_STAGE(0, 0); cpa_commit();
  LOAD_STAGE(1, 1); cpa_commit();
  LOAD_STAGE(2, 2); cpa_commit();

  const int aRow = (lane & 7) + ((lane >> 3) & 1) * 8;
  const int aCol = ((lane >> 4) & 1) * 8;
  const int bRow = (lane & 7) + ((lane >> 4) & 1) * 8;
  const int bCol = ((lane >> 3) & 1) * 8;

  for (int ki = 0; ki < KSTEPS; ki++) {
    const int buf = ki & 3;
    cpa_wait<2>();
    __syncthreads();
    if (ki + 3 < KSTEPS) LOAD_STAGE((ki + 3) & 3, ki + 3);
    cpa_commit();

    const uint32_t aB = sm + SM_AH + buf * STAGE_A_B;
    const uint32_t alB = sm + SM_AL + buf * STAGE_A_B;
    const uint32_t bB = sm + SM_BH + buf * STAGE_B_B;
    const uint32_t blB = sm + SM_BL + buf * STAGE_B_B;

    uint32_t ah[2][4], al[2][4], bh[6][2], bl[6][2];
#pragma unroll
    for (int ti = 0; ti < 2; ti++) {
      uint32_t off = (uint32_t)(((wm0 + ti * 16 + aRow) * ST + aCol) * 2);
      ldsm4(ah[ti], aB + off);
      ldsm4(al[ti], alB + off);
    }
#pragma unroll
    for (int p = 0; p < 3; p++) {
      uint32_t off = (uint32_t)(((wn0 + p * 16 + bRow) * ST + bCol) * 2);
      uint32_t t[4];
      ldsm4(t, bB + off);
      bh[2 * p][0] = t[0]; bh[2 * p][1] = t[1];
      bh[2 * p + 1][0] = t[2]; bh[2 * p + 1][1] = t[3];
      ldsm4(t, blB + off);
      bl[2 * p][0] = t[0]; bl[2 * p][1] = t[1];
      bl[2 * p + 1][0] = t[2]; bl[2 * p + 1][1] = t[3];
    }
#pragma unroll
    for (int ti = 0; ti < 2; ti++)
#pragma unroll
      for (int nj = 0; nj < 6; nj++) {
        mma_bf16(acc[ti][nj], ah[ti], bh[nj]);
        mma_bf16(acc[ti][nj], ah[ti], bl[nj]);
        mma_bf16(acc[ti][nj], al[ti], bh[nj]);
      }
  }
#undef LOAD_STAGE

  // epilogue
  const int g = lane >> 2, tq = lane & 3;
#pragma unroll
  for (int ti = 0; ti < 2; ti++) {
    int m = m0 + wm0 + ti * 16 + g;
#pragma unroll
    for (int nj = 0; nj < 6; nj++) {
      int n = n0 + wn0 + nj * 8 + tq * 2;
      int seg = n / NSEG, nr = n - seg * NSEG;
      if (nr >= nwrite) continue;
      int col = seg * segstride + nr;
      float b0 = bias[n], b1 = bias[n + 1];
      if (m < M)
        *(float2*)(out + (size_t)m * ldout + col) =
            make_float2(acc[ti][nj][0] + b0, acc[ti][nj][1] + b1);
      if (m + 8 < M)
        *(float2*)(out + (size_t)(m + 8) * ldout + col) =
            make_float2(acc[ti][nj][2] + b0, acc[ti][nj][3] + b1);
    }
  }
}

// ---------------- attention (per sample) ----------------
template <int LAYER>
__global__ __launch_bounds__(256) void attn_kernel(const int* __restrict__ neighbors, int B) {
  __shared__ float q[E_];
  __shared__ float kk[KNB][E_];
  __shared__ float sc[HH][KNB];
  __shared__ float at[HH][KNB];
  __shared__ const float* akp[KNB];
  __shared__ const float* bkp[KNB];
  __shared__ int pad[KNB];

  const int b = blockIdx.x;
  const int tid = threadIdx.x;
  const float* trow = g_tqkv + (size_t)b * 576;

  if (tid < KNB) {
    int nb = neighbors[b * KNB + tid];
    pad[tid] = (nb == 0) ? 1 : 0;
    const float* ap = g_node_kv + (size_t)nb * 384;
    if (LAYER == 1) {
      int ow = g_owner[nb];
      if (ow >= 0) ap = g_upd_kv + (size_t)ow * 384;
    }
    akp[tid] = ap;
    bkp[tid] = g_edge_kv + ((size_t)b * KNB + tid) * 384;
  }
  if (tid < E_) q[tid] = g_qh[(size_t)b * KP + tid] + trow[tid];
  __syncthreads();

  const float* tk = trow + NSEG;
  for (int idx = tid; idx < KNB * E_; idx += 256) {
    int j = idx / E_, e = idx - j * E_;
    kk[j][e] = akp[j][e] + bkp[j][e] + tk[e];
  }
  if (tid == 0) {
    int all = 1;
#pragma unroll
    for (int j = 0; j < KNB; j++) all &= pad[j];
    if (all) pad[0] = 0;
  }
  __syncthreads();

  if (tid < HH * KNB) {
    int h = tid / KNB, j = tid - h * KNB;
    const float* qp = q + h * HD_;
    const float* kp = &kk[j][h * HD_];
    float sum = 0.f;
#pragma unroll
    for (int d = 0; d < HD_; d++) sum += qp[d] * kp[d];
    sum *= 0.10783277320343841f;
    if (pad[j]) sum = -1e9f;
    sc[h][j] = sum;
  }
  __syncthreads();

  if (tid < HH) {
    float m = -INFINITY;
#pragma unroll
    for (int j = 0; j < KNB; j++) m = fmaxf(m, sc[tid][j]);
    float ex[KNB], ssum = 0.f;
#pragma unroll
    for (int j = 0; j < KNB; j++) { ex[j] = expf(sc[tid][j] - m); ssum += ex[j]; }
    float inv = 1.f / ssum;
#pragma unroll
    for (int j = 0; j < KNB; j++) at[tid][j] = ex[j] * inv;
  }
  __syncthreads();

  if (tid < E_) {
    int h = tid / HD_;
    float o = trow[2 * NSEG + tid];  // t_v (includes bv); sum(attn)==1
#pragma unroll
    for (int j = 0; j < KNB; j++)
      o += at[h][j] * (akp[j][NSEG + tid] + bkp[j][NSEG + tid]);
    g_o[(size_t)b * KP + tid] = o;
  }
}

// ---------------- launch ----------------
static inline int cdiv(int a, int b) { return (a + b - 1) / b; }

extern "C" void kernel_launch(void* const* d_in, const int* in_sizes, int n_in,
                              void* d_out, int out_size) {
  const int* nodes     = (const int*)d_in[0];
  const float* ts      = (const float*)d_in[1];
  const int* neighbors = (const int*)d_in[2];
  const int* eidx      = (const int*)d_in[3];
  const float* nf      = (const float*)d_in[4];
  const float* ef      = (const float*)d_in[5];
  const float* time_w  = (const float*)d_in[6];
  const float* time_b  = (const float*)d_in[7];
  const float* q_w     = (const float*)d_in[8];
  const float* k_w     = (const float*)d_in[9];
  const float* v_w     = (const float*)d_in[10];
  const float* bq      = (const float*)d_in[11];
  const float* bk      = (const float*)d_in[12];
  const float* bv      = (const float*)d_in[13];
  const float* out_w   = (const float*)d_in[14];
  const float* out_b   = (const float*)d_in[15];
  float* out = (float*)d_out;
  const int B = in_sizes[0];

  __nv_bfloat16 *pWhi, *pWlo, *pAhi, *pAlo;
  float *pWb, *ptqkv, *pnodekv, *pedgekv, *pupdkv, *pqh, *po, *ph1;
  cudaGetSymbolAddress((void**)&pWhi, g_Whi);
  cudaGetSymbolAddress((void**)&pWlo, g_Wlo);
  cudaGetSymbolAddress((void**)&pWb, g_Wb);
  cudaGetSymbolAddress((void**)&pAhi, g_Ahi);
  cudaGetSymbolAddress((void**)&pAlo, g_Alo);
  cudaGetSymbolAddress((void**)&ptqkv, g_tqkv);
  cudaGetSymbolAddress((void**)&pnodekv, g_node_kv);
  cudaGetSymbolAddress((void**)&pedgekv, g_edge_kv);
  cudaGetSymbolAddress((void**)&pupdkv, g_upd_kv);
  cudaGetSymbolAddress((void**)&pqh, g_qh);
  cudaGetSymbolAddress((void**)&po, g_o);
  cudaGetSymbolAddress((void**)&ph1, g_h1);

  cudaFuncSetAttribute(mma_gemm_kernel, cudaFuncAttributeMaxDynamicSharedMemorySize, SMEM_G);

  init_owner_kernel<<<cdiv(NNODES, 256), 256>>>();
  cudaMemsetAsync(pWhi, 0, (size_t)PPAD * KP * sizeof(__nv_bfloat16));
  cudaMemsetAsync(pWlo, 0, (size_t)PPAD * KP * sizeof(__nv_bfloat16));
  cudaMemsetAsync(pWb, 0, (size_t)PPAD * sizeof(float));

  // ---- weight packs ----
  PArgs p;
  p.w[0] = q_w; p.ld[0] = E_;     p.coff[0] = 0;  p.bias[0] = bq;
  p.w[1] = k_w; p.ld[1] = 2 * E_; p.coff[1] = 0;  p.bias[1] = bk;
  p.w[2] = v_w; p.ld[2] = 2 * E_; p.coff[2] = 0;  p.bias[2] = bv;
  pack_w_kernel<<<cdiv(3 * NSEG * KP, 256), 256>>>(p, 3, pWhi + (size_t)P1_OFF * KP, pWlo + (size_t)P1_OFF * KP, pWb + P1_OFF);
  p.bias[0] = nullptr; p.bias[1] = nullptr; p.bias[2] = nullptr;
  p.w[0] = k_w; p.ld[0] = 2 * E_; p.coff[0] = 0;
  p.w[1] = v_w; p.ld[1] = 2 * E_; p.coff[1] = 0;
  pack_w_kernel<<<cdiv(2 * NSEG * KP, 256), 256>>>(p, 2, pWhi + (size_t)P2_OFF * KP, pWlo + (size_t)P2_OFF * KP, pWb + P2_OFF);
  p.coff[0] = E_; p.coff[1] = E_;
  pack_w_kernel<<<cdiv(2 * NSEG * KP, 256), 256>>>(p, 2, pWhi + (size_t)P3_OFF * KP, pWlo + (size_t)P3_OFF * KP, pWb + P3_OFF);
  p.w[0] = q_w; p.ld[0] = E_; p.coff[0] = 0;
  pack_w_kernel<<<cdiv(NSEG * KP, 256), 256>>>(p, 1, pWhi + (size_t)P4_OFF * KP, pWlo + (size_t)P4_OFF * KP, pWb + P4_OFF);
  p.w[0] = out_w; p.bias[0] = out_b;
  pack_w_kernel<<<cdiv(NSEG * KP, 256), 256>>>(p, 1, pWhi + (size_t)P5_OFF * KP, pWlo + (size_t)P5_OFF * KP, pWb + P5_OFF);

#define GEMM(Mpad, Npad, poff, outp, M, ldo, segs, nw)                        \
  mma_gemm_kernel<<<dim3((Npad) / BN, (Mpad) / BM), 256, SMEM_G>>>(           \
      pAhi, pAlo, pWhi + (size_t)(poff) * KP, pWlo + (size_t)(poff) * KP,     \
      pWb + (poff), outp, M, ldo, segs, nw)

  // t -> tqkv
  timeconv_kernel<<<cdiv(BPAD * KP, 256), 256>>>(ts, time_w, time_b, B, BPAD);
  GEMM(BPAD, 576, P1_OFF, ptqkv, B, 576, NSEG, NSEG);

  // nf -> node kv
  convert_kernel<<<cdiv(NPADN * KP, 256), 256>>>(nf, E_, nullptr, 0, NNODES, NPADN);
  GEMM(NPADN, 384, P2_OFF, pnodekv, NNODES, 384, NSEG, NSEG);

  // gathered ef -> edge kv
  convert_kernel<<<cdiv(NSLOT * KP, 256), 256>>>(ef, E_, eidx, 1, B * KNB, NSLOT);
  GEMM(NSLOT, 384, P3_OFF, pedgekv, B * KNB, 384, NSEG, NSEG);

  // ---- layer 0 ----
  convert_kernel<<<cdiv(BPAD * KP, 256), 256>>>(nf, E_, nodes, 1, B, BPAD);
  GEMM(BPAD, NSEG, P4_OFF, pqh, B, KP, 0, KP);

  attn_kernel<0><<<B, 256>>>(neighbors, B);

  convert_kernel<<<cdiv(BPAD * KP, 256), 256>>>(po, KP, nullptr, 0, B, BPAD);
  GEMM(BPAD, NSEG, P5_OFF, ph1, B, KP, 0, KP);

  build_owner_kernel<<<cdiv(B, 256), 256>>>(nodes, B);

  // ---- layer 1 ----
  convert_kernel<<<cdiv(BPAD * KP, 256), 256>>>(ph1, KP, nodes, 2, B, BPAD);
  GEMM(BPAD, NSEG, P4_OFF, pqh, B, KP, 0, KP);

  convert_kernel<<<cdiv(BPAD * KP, 256), 256>>>(ph1, KP, nullptr, 0, B, BPAD);
  GEMM(BPAD, 384, P2_OFF, pupdkv, B, 384, NSEG, NSEG);

  attn_kernel<1><<<B, 256>>>(neighbors, B);

  convert_kernel<<<cdiv(BPAD * KP, 256), 256>>>(po, KP, nullptr, 0, B, BPAD);
  GEMM(BPAD, NSEG, P5_OFF, out, B, E_, 0, E_);
#undef GEMM
}

// round 6
// speedup vs baseline: 6.6725x; 1.0186x over previous
#include <cuda_runtime.h>
#include <cuda_bf16.h>
#include <math.h>
#include <stdint.h>

#define E_ 172
#define KP 176            // padded K (11 k16 steps)
#define KSTEPS 11
#define NSEG 192          // padded N per weight segment
#define KNB 20
#define HH 2
#define HD_ 86
#define NNODES 100000
#define BMAX 12000
#define BPAD 12032        // 94*128
#define NPADN 100096      // 782*128
#define NSLOT 240000      // 1875*128

// pack row offsets within the packed weight buffer (rows of KP cols)
#define P1_OFF 0      // tqkv: 3 segs (q,kE,vE) + biases        N=576
#define P2_OFF 576    // node/upd kv: (kE, vE)                  N=384
#define P3_OFF 960    // edge kv: (kD, vD)                      N=384
#define P4_OFF 1344   // q proj                                 N=192
#define P5_OFF 1536   // out proj + bias                        N=192
#define PTOT 1728

// ---------------- scratch ----------------
__device__ __nv_bfloat16 g_Ahi[(size_t)NSLOT * KP];
__device__ __nv_bfloat16 g_Alo[(size_t)NSLOT * KP];
__device__ __nv_bfloat16 g_Whi[(size_t)PTOT * KP];
__device__ __nv_bfloat16 g_Wlo[(size_t)PTOT * KP];
__device__ float g_Wb[PTOT];

__device__ float g_tqkv[BMAX * 576];
__device__ float g_node_kv[(size_t)NNODES * 384];
__device__ float g_edge_kv[(size_t)NSLOT * 384];
__device__ float g_upd_kv[BMAX * 384];
__device__ float g_qh[BMAX * KP];
__device__ __nv_bfloat16 g_H1hi[BPAD * KP];   // layer-0 output, bf16 split
__device__ __nv_bfloat16 g_H1lo[BPAD * KP];
__device__ int g_owner[NNODES];

// ---------------- helpers ----------------
__device__ __forceinline__ void cpa16(uint32_t dst, const void* src) {
  asm volatile("cp.async.cg.shared.global [%0], [%1], 16;" :: "r"(dst), "l"(src));
}
__device__ __forceinline__ void cpa_commit() { asm volatile("cp.async.commit_group;" ::: "memory"); }
template <int N>
__device__ __forceinline__ void cpa_wait() { asm volatile("cp.async.wait_group %0;" :: "n"(N) : "memory"); }

__device__ __forceinline__ void ldsm4(uint32_t* r, uint32_t addr) {
  asm volatile("ldmatrix.sync.aligned.m8n8.x4.shared.b16 {%0,%1,%2,%3}, [%4];"
               : "=r"(r[0]), "=r"(r[1]), "=r"(r[2]), "=r"(r[3]) : "r"(addr));
}
__device__ __forceinline__ void mma_bf16(float* d, const uint32_t* a, const uint32_t* b) {
  asm volatile(
      "mma.sync.aligned.m16n8k16.row.col.f32.bf16.bf16.f32 "
      "{%0,%1,%2,%3},{%4,%5,%6,%7},{%8,%9},{%0,%1,%2,%3};"
      : "+f"(d[0]), "+f"(d[1]), "+f"(d[2]), "+f"(d[3])
      : "r"(a[0]), "r"(a[1]), "r"(a[2]), "r"(a[3]), "r"(b[0]), "r"(b[1]));
}

__device__ __forceinline__ void bf16split(float v, __nv_bfloat16& h, __nv_bfloat16& l) {
  h = __float2bfloat16(v);
  l = __float2bfloat16(v - __bfloat162float(h));
}

// ---------------- small kernels ----------------
__global__ void init_owner_kernel() {
  int i = blockIdx.x * blockDim.x + threadIdx.x;
  if (i < NNODES) g_owner[i] = -1;
}
__global__ void build_owner_kernel(const int* __restrict__ nodes, int B) {
  int i = blockIdx.x * blockDim.x + threadIdx.x;
  if (i < B) atomicMax(&g_owner[nodes[i]], i);
}

// ---------------- weight packing ----------------
struct PArgs {
  const float* w[3];
  int ld[3];
  int coff[3];
  const float* bias[3];
};
__global__ void pack_w_kernel(PArgs a, int nseg, __nv_bfloat16* whi,
                              __nv_bfloat16* wlo, float* pbias) {
  int i = blockIdx.x * blockDim.x + threadIdx.x;
  int tot = nseg * NSEG * KP;
  if (i >= tot) return;
  int n = i / KP, c = i - n * KP;
  int seg = n / NSEG, nr = n - seg * NSEG;
  float v = 0.f;
  if (nr < E_ && c < E_) v = a.w[seg][(size_t)nr * a.ld[seg] + a.coff[seg] + c];
  __nv_bfloat16 h, l;
  bf16split(v, h, l);
  whi[i] = h; wlo[i] = l;
  if (c == 0) pbias[n] = (nr < E_ && a.bias[seg]) ? a.bias[seg][nr] : 0.f;
}

// ---------------- input conversion (optional gather) ----------------
__global__ void convert_kernel(const float* __restrict__ X, int ldx,
                               const int* __restrict__ g1, int gmode,
                               int M, int Mpad) {
  int i = blockIdx.x * blockDim.x + threadIdx.x;
  if (i >= Mpad * KP) return;
  int r = i / KP, c = i - r * KP;
  float v = 0.f;
  if (r < M && c < E_) {
    int src = r;
    if (gmode >= 1) src = g1[r];
    v = X[(size_t)src * ldx + c];
  }
  __nv_bfloat16 h, l;
  bf16split(v, h, l);
  g_Ahi[i] = h; g_Alo[i] = l;
}

__global__ void timeconv_kernel(const float* __restrict__ ts,
                                const float* __restrict__ tw,
                                const float* __restrict__ tb, int B, int Mpad) {
  int i = blockIdx.x * blockDim.x + threadIdx.x;
  if (i >= Mpad * KP) return;
  int r = i / KP, c = i - r * KP;
  float v = 0.f;
  if (r < B && c < E_) {
    float arg = __fadd_rn(__fmul_rn(ts[r], tw[c]), tb[c]);
    v = (float)cos((double)arg);
  }
  __nv_bfloat16 h, l;
  bf16split(v, h, l);
  g_Ahi[i] = h; g_Alo[i] = l;
}

// gather h1 rows (bf16 split) for layer-1 q: A[r] = H1[owner[nodes[r]]]
__global__ void gather_h1_kernel(const int* __restrict__ nodes, int B, int Mpad) {
  int i = blockIdx.x * blockDim.x + threadIdx.x;
  if (i >= Mpad * KP) return;
  int r = i / KP, c = i - r * KP;
  __nv_bfloat16 h = __float2bfloat16(0.f), l = h;
  if (r < B) {
    int src = g_owner[nodes[r]];
    h = g_H1hi[(size_t)src * KP + c];
    l = g_H1lo[(size_t)src * KP + c];
  }
  g_Ahi[i] = h; g_Alo[i] = l;
}

// ---------------- pipelined bf16 HMMA GEMM ----------------
#define BM 128
#define BN 96
#define ST 24
#define STAGE_A_B (BM * ST * 2)
#define STAGE_B_B (BN * ST * 2)
#define SM_AH 0
#define SM_AL (SM_AH + 4 * STAGE_A_B)
#define SM_BH (SM_AL + 4 * STAGE_A_B)
#define SM_BL (SM_BH + 4 * STAGE_B_B)
#define SMEM_G (SM_BL + 4 * STAGE_B_B)

__global__ __launch_bounds__(256, 2) void mma_gemm_kernel(
    const __nv_bfloat16* __restrict__ Ahi, const __nv_bfloat16* __restrict__ Alo,
    const __nv_bfloat16* __restrict__ Whi, const __nv_bfloat16* __restrict__ Wlo,
    const float* __restrict__ bias, float* __restrict__ out,
    __nv_bfloat16* __restrict__ ohi, __nv_bfloat16* __restrict__ olo,
    int M, int ldout, int segstride, int nwrite) {
  extern __shared__ __align__(128) char smraw[];
  const uint32_t sm = (uint32_t)__cvta_generic_to_shared(smraw);
  const int tid = threadIdx.x;
  const int warp = tid >> 5, lane = tid & 31;
  const int m0 = blockIdx.y * BM;
  const int n0 = blockIdx.x * BN;
  const int wm0 = (warp >> 1) * 32;
  const int wn0 = (warp & 1) * 48;

  float acc[2][6][4];
#pragma unroll
  for (int i = 0; i < 2; i++)
#pragma unroll
    for (int j = 0; j < 6; j++)
#pragma unroll
      for (int k = 0; k < 4; k++) acc[i][j][k] = 0.f;

  const int lr = tid >> 1, lch = tid & 1;
  const size_t srcA = (size_t)(m0 + lr) * KP + lch * 8;
  const size_t srcB = (size_t)(n0 + lr) * KP + lch * 8;
  const uint32_t dstAoff = (uint32_t)((lr * ST + lch * 8) * 2);
  const uint32_t dstBoff = dstAoff;

#define LOAD_STAGE(buf, ki)                                                   \
  do {                                                                        \
    cpa16(sm + SM_AH + (buf) * STAGE_A_B + dstAoff, Ahi + srcA + (ki) * 16);  \
    cpa16(sm + SM_AL + (buf) * STAGE_A_B + dstAoff, Alo + srcA + (ki) * 16);  \
    if (tid < 2 * BN) {                                                       \
      cpa16(sm + SM_BH + (buf) * STAGE_B_B + dstBoff, Whi + srcB + (ki) * 16);\
      cpa16(sm + SM_BL + (buf) * STAGE_B_B + dstBoff, Wlo + srcB + (ki) * 16);\
    }                                                                         \
  } while (0)

  LOAD_STAGE(0, 0); cpa_commit();
  LOAD_STAGE(1, 1); cpa_commit();
  LOAD_STAGE(2, 2); cpa_commit();

  const int aRow = (lane & 7) + ((lane >> 3) & 1) * 8;
  const int aCol = ((lane >> 4) & 1) * 8;
  const int bRow = (lane & 7) + ((lane >> 4) & 1) * 8;
  const int bCol = ((lane >> 3) & 1) * 8;

  for (int ki = 0; ki < KSTEPS; ki++) {
    const int buf = ki & 3;
    cpa_wait<2>();
    __syncthreads();
    if (ki + 3 < KSTEPS) LOAD_STAGE((ki + 3) & 3, ki + 3);
    cpa_commit();

    const uint32_t aB = sm + SM_AH + buf * STAGE_A_B;
    const uint32_t alB = sm + SM_AL + buf * STAGE_A_B;
    const uint32_t bB = sm + SM_BH + buf * STAGE_B_B;
    const uint32_t blB = sm + SM_BL + buf * STAGE_B_B;

    uint32_t ah[2][4], al[2][4], bh[6][2], bl[6][2];
#pragma unroll
    for (int ti = 0; ti < 2; ti++) {
      uint32_t off = (uint32_t)(((wm0 + ti * 16 + aRow) * ST + aCol) * 2);
      ldsm4(ah[ti], aB + off);
      ldsm4(al[ti], alB + off);
    }
#pragma unroll
    for (int p = 0; p < 3; p++) {
      uint32_t off = (uint32_t)(((wn0 + p * 16 + bRow) * ST + bCol) * 2);
      uint32_t t[4];
      ldsm4(t, bB + off);
      bh[2 * p][0] = t[0]; bh[2 * p][1] = t[1];
      bh[2 * p + 1][0] = t[2]; bh[2 * p + 1][1] = t[3];
      ldsm4(t, blB + off);
      bl[2 * p][0] = t[0]; bl[2 * p][1] = t[1];
      bl[2 * p + 1][0] = t[2]; bl[2 * p + 1][1] = t[3];
    }
#pragma unroll
    for (int ti = 0; ti < 2; ti++)
#pragma unroll
      for (int nj = 0; nj < 6; nj++) {
        mma_bf16(acc[ti][nj], ah[ti], bh[nj]);
        mma_bf16(acc[ti][nj], ah[ti], bl[nj]);
        mma_bf16(acc[ti][nj], al[ti], bh[nj]);
      }
  }
#undef LOAD_STAGE

  // epilogue
  const int g = lane >> 2, tq = lane & 3;
#pragma unroll
  for (int ti = 0; ti < 2; ti++) {
    int m = m0 + wm0 + ti * 16 + g;
#pragma unroll
    for (int nj = 0; nj < 6; nj++) {
      int n = n0 + wn0 + nj * 8 + tq * 2;
      int seg = n / NSEG, nr = n - seg * NSEG;
      if (nr >= nwrite) continue;
      int col = seg * segstride + nr;
      float b0 = bias[n], b1 = bias[n + 1];
#pragma unroll
      for (int half = 0; half < 2; half++) {
        int mm = m + half * 8;
        if (mm >= M) continue;
        float v0 = acc[ti][nj][2 * half] + b0;
        float v1 = acc[ti][nj][2 * half + 1] + b1;
        if (out) {
          *(float2*)(out + (size_t)mm * ldout + col) = make_float2(v0, v1);
        } else {
          __nv_bfloat16 h0, l0, h1, l1;
          bf16split(v0, h0, l0);
          bf16split(v1, h1, l1);
          *(__nv_bfloat162*)(ohi + (size_t)mm * KP + col) = __nv_bfloat162(h0, h1);
          *(__nv_bfloat162*)(olo + (size_t)mm * KP + col) = __nv_bfloat162(l0, l1);
        }
      }
    }
  }
}

// ---------------- attention (per sample), writes bf16-split output ----------------
template <int LAYER>
__global__ __launch_bounds__(256) void attn_kernel(const int* __restrict__ neighbors, int B) {
  __shared__ float q[E_];
  __shared__ float kk[KNB][E_];
  __shared__ float sc[HH][KNB];
  __shared__ float at[HH][KNB];
  __shared__ const float* akp[KNB];
  __shared__ const float* bkp[KNB];
  __shared__ int pad[KNB];

  const int b = blockIdx.x;
  const int tid = threadIdx.x;
  const float* trow = g_tqkv + (size_t)b * 576;

  if (tid < KNB) {
    int nb = neighbors[b * KNB + tid];
    pad[tid] = (nb == 0) ? 1 : 0;
    const float* ap = g_node_kv + (size_t)nb * 384;
    if (LAYER == 1) {
      int ow = g_owner[nb];
      if (ow >= 0) ap = g_upd_kv + (size_t)ow * 384;
    }
    akp[tid] = ap;
    bkp[tid] = g_edge_kv + ((size_t)b * KNB + tid) * 384;
  }
  if (tid < E_) q[tid] = g_qh[(size_t)b * KP + tid] + trow[tid];
  __syncthreads();

  const float* tk = trow + NSEG;
  for (int idx = tid; idx < KNB * E_; idx += 256) {
    int j = idx / E_, e = idx - j * E_;
    kk[j][e] = akp[j][e] + bkp[j][e] + tk[e];
  }
  if (tid == 0) {
    int all = 1;
#pragma unroll
    for (int j = 0; j < KNB; j++) all &= pad[j];
    if (all) pad[0] = 0;
  }
  __syncthreads();

  if (tid < HH * KNB) {
    int h = tid / KNB, j = tid - h * KNB;
    const float* qp = q + h * HD_;
    const float* kp = &kk[j][h * HD_];
    float sum = 0.f;
#pragma unroll
    for (int d = 0; d < HD_; d++) sum += qp[d] * kp[d];
    sum *= 0.10783277320343841f;
    if (pad[j]) sum = -1e9f;
    sc[h][j] = sum;
  }
  __syncthreads();

  if (tid < HH) {
    float m = -INFINITY;
#pragma unroll
    for (int j = 0; j < KNB; j++) m = fmaxf(m, sc[tid][j]);
    float ex[KNB], ssum = 0.f;
#pragma unroll
    for (int j = 0; j < KNB; j++) { ex[j] = expf(sc[tid][j] - m); ssum += ex[j]; }
    float inv = 1.f / ssum;
#pragma unroll
    for (int j = 0; j < KNB; j++) at[tid][j] = ex[j] * inv;
  }
  __syncthreads();

  if (tid < E_) {
    int h = tid / HD_;
    float o = trow[2 * NSEG + tid];  // t_v (includes bv); sum(attn)==1
#pragma unroll
    for (int j = 0; j < KNB; j++)
      o += at[h][j] * (akp[j][NSEG + tid] + bkp[j][NSEG + tid]);
    __nv_bfloat16 hh, ll;
    bf16split(o, hh, ll);
    g_Ahi[(size_t)b * KP + tid] = hh;
    g_Alo[(size_t)b * KP + tid] = ll;
  }
}

// ---------------- launch ----------------
static inline int cdiv(int a, int b) { return (a + b - 1) / b; }

extern "C" void kernel_launch(void* const* d_in, const int* in_sizes, int n_in,
                              void* d_out, int out_size) {
  const int* nodes     = (const int*)d_in[0];
  const float* ts      = (const float*)d_in[1];
  const int* neighbors = (const int*)d_in[2];
  const int* eidx      = (const int*)d_in[3];
  const float* nf      = (const float*)d_in[4];
  const float* ef      = (const float*)d_in[5];
  const float* time_w  = (const float*)d_in[6];
  const float* time_b  = (const float*)d_in[7];
  const float* q_w     = (const float*)d_in[8];
  const float* k_w     = (const float*)d_in[9];
  const float* v_w     = (const float*)d_in[10];
  const float* bq      = (const float*)d_in[11];
  const float* bk      = (const float*)d_in[12];
  const float* bv      = (const float*)d_in[13];
  const float* out_w   = (const float*)d_in[14];
  const float* out_b   = (const float*)d_in[15];
  float* out = (float*)d_out;
  const int B = in_sizes[0];

  __nv_bfloat16 *pWhi, *pWlo, *pAhi, *pAlo, *pH1hi, *pH1lo;
  float *pWb, *ptqkv, *pnodekv, *pedgekv, *pupdkv, *pqh;
  cudaGetSymbolAddress((void**)&pWhi, g_Whi);
  cudaGetSymbolAddress((void**)&pWlo, g_Wlo);
  cudaGetSymbolAddress((void**)&pWb, g_Wb);
  cudaGetSymbolAddress((void**)&pAhi, g_Ahi);
  cudaGetSymbolAddress((void**)&pAlo, g_Alo);
  cudaGetSymbolAddress((void**)&pH1hi, g_H1hi);
  cudaGetSymbolAddress((void**)&pH1lo, g_H1lo);
  cudaGetSymbolAddress((void**)&ptqkv, g_tqkv);
  cudaGetSymbolAddress((void**)&pnodekv, g_node_kv);
  cudaGetSymbolAddress((void**)&pedgekv, g_edge_kv);
  cudaGetSymbolAddress((void**)&pupdkv, g_upd_kv);
  cudaGetSymbolAddress((void**)&pqh, g_qh);

  cudaFuncSetAttribute(mma_gemm_kernel, cudaFuncAttributeMaxDynamicSharedMemorySize, SMEM_G);

  PArgs p;

#define GEMMF(Mpad, Npad, poff, outp, M, ldo, segs, nw)                       \
  mma_gemm_kernel<<<dim3((Npad) / BN, (Mpad) / BM), 256, SMEM_G>>>(           \
      pAhi, pAlo, pWhi + (size_t)(poff) * KP, pWlo + (size_t)(poff) * KP,     \
      pWb + (poff), outp, nullptr, nullptr, M, ldo, segs, nw)
#define GEMMB(Mpad, Npad, poff, M)                                            \
  mma_gemm_kernel<<<dim3((Npad) / BN, (Mpad) / BM), 256, SMEM_G>>>(           \
      pAhi, pAlo, pWhi + (size_t)(poff) * KP, pWlo + (size_t)(poff) * KP,     \
      pWb + (poff), nullptr, pH1hi, pH1lo, M, KP, 0, KP)

  // ---- launch order tuned so ncu (-s 5) profiles the edge GEMM ----
  // 0: pack P3 (edge weights)
  p.w[0] = k_w; p.ld[0] = 2 * E_; p.coff[0] = E_; p.bias[0] = nullptr;
  p.w[1] = v_w; p.ld[1] = 2 * E_; p.coff[1] = E_; p.bias[1] = nullptr;
  p.w[2] = nullptr; p.ld[2] = 0; p.coff[2] = 0; p.bias[2] = nullptr;
  pack_w_kernel<<<cdiv(2 * NSEG * KP, 256), 256>>>(p, 2, pWhi + (size_t)P3_OFF * KP, pWlo + (size_t)P3_OFF * KP, pWb + P3_OFF);
  // 1: edge convert (gather ef)
  convert_kernel<<<cdiv(NSLOT * KP, 256), 256>>>(ef, E_, eidx, 1, B * KNB, NSLOT);
  // 2: init owner
  init_owner_kernel<<<cdiv(NNODES, 256), 256>>>();
  // 3: pack P1 (tqkv + biases)
  p.w[0] = q_w; p.ld[0] = E_;     p.coff[0] = 0; p.bias[0] = bq;
  p.w[1] = k_w; p.ld[1] = 2 * E_; p.coff[1] = 0; p.bias[1] = bk;
  p.w[2] = v_w; p.ld[2] = 2 * E_; p.coff[2] = 0; p.bias[2] = bv;
  pack_w_kernel<<<cdiv(3 * NSEG * KP, 256), 256>>>(p, 3, pWhi + (size_t)P1_OFF * KP, pWlo + (size_t)P1_OFF * KP, pWb + P1_OFF);
  // 4: pack P2 (node/upd kv)
  p.w[0] = k_w; p.ld[0] = 2 * E_; p.coff[0] = 0; p.bias[0] = nullptr;
  p.w[1] = v_w; p.ld[1] = 2 * E_; p.coff[1] = 0; p.bias[1] = nullptr;
  p.w[2] = nullptr;
  pack_w_kernel<<<cdiv(2 * NSEG * KP, 256), 256>>>(p, 2, pWhi + (size_t)P2_OFF * KP, pWlo + (size_t)P2_OFF * KP, pWb + P2_OFF);
  // 5: edge GEMM  <-- ncu -s 5 lands here
  GEMMF(NSLOT, 384, P3_OFF, pedgekv, B * KNB, 384, NSEG, NSEG);

  // 6: time encode convert
  timeconv_kernel<<<cdiv(BPAD * KP, 256), 256>>>(ts, time_w, time_b, B, BPAD);
  // 7: tqkv GEMM
  GEMMF(BPAD, 576, P1_OFF, ptqkv, B, 576, NSEG, NSEG);
  // 8: node convert
  convert_kernel<<<cdiv(NPADN * KP, 256), 256>>>(nf, E_, nullptr, 0, NNODES, NPADN);
  // 9: node GEMM
  GEMMF(NPADN, 384, P2_OFF, pnodekv, NNODES, 384, NSEG, NSEG);
  // 10-11: pack P4 (q), P5 (out + bias)
  p.w[0] = q_w; p.ld[0] = E_; p.coff[0] = 0; p.bias[0] = nullptr;
  p.w[1] = nullptr; p.w[2] = nullptr;
  pack_w_kernel<<<cdiv(NSEG * KP, 256), 256>>>(p, 1, pWhi + (size_t)P4_OFF * KP, pWlo + (size_t)P4_OFF * KP, pWb + P4_OFF);
  p.w[0] = out_w; p.bias[0] = out_b;
  pack_w_kernel<<<cdiv(NSEG * KP, 256), 256>>>(p, 1, pWhi + (size_t)P5_OFF * KP, pWlo + (size_t)P5_OFF * KP, pWb + P5_OFF);

  // ---- layer 0 ----
  convert_kernel<<<cdiv(BPAD * KP, 256), 256>>>(nf, E_, nodes, 1, B, BPAD);
  GEMMF(BPAD, NSEG, P4_OFF, pqh, B, KP, 0, KP);
  attn_kernel<0><<<B, 256>>>(neighbors, B);          // writes bf16 into g_Ahi/g_Alo
  GEMMB(BPAD, NSEG, P5_OFF, B);                      // h1 -> bf16 split buffers
  build_owner_kernel<<<cdiv(B, 256), 256>>>(nodes, B);

  // ---- layer 1 ----
  // updkv GEMM reads H1 bf16 buffers directly as A
  mma_gemm_kernel<<<dim3(384 / BN, BPAD / BM), 256, SMEM_G>>>(
      pH1hi, pH1lo, pWhi + (size_t)P2_OFF * KP, pWlo + (size_t)P2_OFF * KP,
      pWb + P2_OFF, pupdkv, nullptr, nullptr, B, 384, NSEG, NSEG);
  gather_h1_kernel<<<cdiv(BPAD * KP, 256), 256>>>(nodes, B, BPAD);
  GEMMF(BPAD, NSEG, P4_OFF, pqh, B, KP, 0, KP);
  attn_kernel<1><<<B, 256>>>(neighbors, B);
  GEMMF(BPAD, NSEG, P5_OFF, out, B, E_, 0, E_);
#undef GEMMF
#undef GEMMB
}